// round 1
// baseline (speedup 1.0000x reference)
#include <cuda_runtime.h>

// Problem constants
#define BB 16
#define TT 2048
#define DD 1024
#define HH 64

// Scratch for q, k, v projections: [B*T, H] each, fp32. 8 MB apiece.
__device__ float g_q[BB * TT * HH];
__device__ float g_k[BB * TT * HH];
__device__ float g_v[BB * TT * HH];

// ---------------------------------------------------------------------------
// Kernel 1: fused projection. q/k/v = x @ Wq/Wk/Wv.
// GEMM M=32768, K=1024, N=64 (x3). Block: 64 rows x (64 cols x 3 mats).
// 256 threads as 16x16; each thread owns a 4x4 tile per matrix (48 accums).
// ---------------------------------------------------------------------------
__global__ __launch_bounds__(256) void proj_kernel(
    const float* __restrict__ x,
    const float* __restrict__ Wq,
    const float* __restrict__ Wk,
    const float* __restrict__ Wv)
{
    __shared__ float xs[64][36];        // 64 rows x 32 k, padded to 36 for f4 stores
    __shared__ float ws[3][32][64];     // 3 mats x 32 k x 64 cols

    const int tid = threadIdx.x;
    const int tx = tid & 15;            // col group 0..15
    const int ty = tid >> 4;            // row group 0..15
    const int row0 = blockIdx.x * 64;

    float acc[3][4][4];
#pragma unroll
    for (int m = 0; m < 3; m++)
#pragma unroll
        for (int i = 0; i < 4; i++)
#pragma unroll
            for (int j = 0; j < 4; j++) acc[m][i][j] = 0.f;

    const float* const Wm[3] = {Wq, Wk, Wv};

    for (int k0 = 0; k0 < DD; k0 += 32) {
        // Load x tile: 64x32 floats = 512 float4; 2 per thread.
        {
            const int r  = tid >> 3;         // 0..31
            const int c4 = (tid & 7) * 4;    // 0,4,..,28
            *(float4*)&xs[r][c4] =
                *(const float4*)&x[(size_t)(row0 + r) * DD + k0 + c4];
            *(float4*)&xs[r + 32][c4] =
                *(const float4*)&x[(size_t)(row0 + r + 32) * DD + k0 + c4];
        }
        // Load W tiles: per matrix 32x64 floats = 512 float4; 2 per thread.
        {
            const int r  = tid >> 4;         // 0..15
            const int c4 = (tid & 15) * 4;   // 0,4,..,60
#pragma unroll
            for (int m = 0; m < 3; m++) {
                *(float4*)&ws[m][r][c4] =
                    *(const float4*)&Wm[m][(size_t)(k0 + r) * HH + c4];
                *(float4*)&ws[m][r + 16][c4] =
                    *(const float4*)&Wm[m][(size_t)(k0 + r + 16) * HH + c4];
            }
        }
        __syncthreads();

#pragma unroll
        for (int kk = 0; kk < 32; kk++) {
            float a[4];
#pragma unroll
            for (int i = 0; i < 4; i++) a[i] = xs[ty * 4 + i][kk];
            float4 bq = *(const float4*)&ws[0][kk][tx * 4];
            float4 bk = *(const float4*)&ws[1][kk][tx * 4];
            float4 bv = *(const float4*)&ws[2][kk][tx * 4];
#pragma unroll
            for (int i = 0; i < 4; i++) {
                acc[0][i][0] += a[i] * bq.x;  acc[0][i][1] += a[i] * bq.y;
                acc[0][i][2] += a[i] * bq.z;  acc[0][i][3] += a[i] * bq.w;
                acc[1][i][0] += a[i] * bk.x;  acc[1][i][1] += a[i] * bk.y;
                acc[1][i][2] += a[i] * bk.z;  acc[1][i][3] += a[i] * bk.w;
                acc[2][i][0] += a[i] * bv.x;  acc[2][i][1] += a[i] * bv.y;
                acc[2][i][2] += a[i] * bv.z;  acc[2][i][3] += a[i] * bv.w;
            }
        }
        __syncthreads();
    }

    // Write results
#pragma unroll
    for (int i = 0; i < 4; i++) {
        const size_t off = (size_t)(row0 + ty * 4 + i) * HH + tx * 4;
        float4 t;
        t.x = acc[0][i][0]; t.y = acc[0][i][1]; t.z = acc[0][i][2]; t.w = acc[0][i][3];
        *(float4*)&g_q[off] = t;
        t.x = acc[1][i][0]; t.y = acc[1][i][1]; t.z = acc[1][i][2]; t.w = acc[1][i][3];
        *(float4*)&g_k[off] = t;
        t.x = acc[2][i][0]; t.y = acc[2][i][1]; t.z = acc[2][i][2]; t.w = acc[2][i][3];
        *(float4*)&g_v[off] = t;
    }
}

// ---------------------------------------------------------------------------
// Kernel 2: causal flash attention, fp32.
// Grid (T/64, B). Block 128 threads. Thread = (query row r = tid/2,
// half of head dim hh = (tid&1)*32). Online softmax over 16-key chunks.
// Only processes lower-triangular key tiles (kt <= qt).
// ---------------------------------------------------------------------------
__global__ __launch_bounds__(128) void attn_kernel(float* __restrict__ out)
{
    __shared__ float Ks[64][68];
    __shared__ float Vs[64][68];

    const int tid = threadIdx.x;
    const int b   = blockIdx.y;
    const int qt  = blockIdx.x;
    const int r   = tid >> 1;             // 0..63 query row in tile
    const int hh  = (tid & 1) * 32;       // 0 or 32
    const int qrow = qt * 64 + r;
    const float scale = 0.125f;           // 1/sqrt(64)

    float qreg[32];
    {
        const float* qp = &g_q[((size_t)b * TT + qrow) * HH + hh];
#pragma unroll
        for (int i = 0; i < 8; i++) {
            float4 t = *(const float4*)&qp[i * 4];
            qreg[i * 4 + 0] = t.x * scale;
            qreg[i * 4 + 1] = t.y * scale;
            qreg[i * 4 + 2] = t.z * scale;
            qreg[i * 4 + 3] = t.w * scale;
        }
    }

    float m = -1e30f, l = 0.f;
    float o[32];
#pragma unroll
    for (int i = 0; i < 32; i++) o[i] = 0.f;

    for (int kt = 0; kt <= qt; kt++) {
        const float* kp = &g_k[((size_t)b * TT + kt * 64) * HH];
        const float* vp = &g_v[((size_t)b * TT + kt * 64) * HH];

        __syncthreads();   // previous tile fully consumed
#pragma unroll
        for (int t = 0; t < 8; t++) {
            const int idx = tid + t * 128;      // 0..1023 float4 slots
            const int rr  = idx >> 4;
            const int c4  = (idx & 15) * 4;
            *(float4*)&Ks[rr][c4] = *(const float4*)&kp[(size_t)rr * HH + c4];
            *(float4*)&Vs[rr][c4] = *(const float4*)&vp[(size_t)rr * HH + c4];
        }
        __syncthreads();

        const int jmax = (kt == qt) ? r : 63;   // causal: key j valid iff j <= jmax

#pragma unroll 1
        for (int c = 0; c < 4; c++) {
            float s[16];
#pragma unroll
            for (int jj = 0; jj < 16; jj++) {
                const int j = c * 16 + jj;
                float p = 0.f;
#pragma unroll
                for (int i = 0; i < 32; i += 4) {
                    float4 kv = *(const float4*)&Ks[j][hh + i];
                    p += qreg[i]     * kv.x + qreg[i + 1] * kv.y
                       + qreg[i + 2] * kv.z + qreg[i + 3] * kv.w;
                }
                p += __shfl_xor_sync(0xffffffffu, p, 1);   // full 64-dim dot
                s[jj] = (j <= jmax) ? p : -1e30f;
            }

            float mn = m;
#pragma unroll
            for (int jj = 0; jj < 16; jj++) mn = fmaxf(mn, s[jj]);

            const float alpha = __expf(m - mn);
            l *= alpha;
#pragma unroll
            for (int i = 0; i < 32; i++) o[i] *= alpha;

#pragma unroll
            for (int jj = 0; jj < 16; jj++) {
                const int j = c * 16 + jj;
                const float p = __expf(s[jj] - mn);
                l += p;
#pragma unroll
                for (int i = 0; i < 32; i += 4) {
                    float4 vv = *(const float4*)&Vs[j][hh + i];
                    o[i]     += p * vv.x;
                    o[i + 1] += p * vv.y;
                    o[i + 2] += p * vv.z;
                    o[i + 3] += p * vv.w;
                }
            }
            m = mn;
        }
    }

    const float inv = 1.f / l;
    float* op = &out[((size_t)b * TT + qrow) * HH + hh];
#pragma unroll
    for (int i = 0; i < 32; i += 4) {
        float4 t;
        t.x = o[i] * inv; t.y = o[i + 1] * inv;
        t.z = o[i + 2] * inv; t.w = o[i + 3] * inv;
        *(float4*)&op[i] = t;
    }
}

// ---------------------------------------------------------------------------
extern "C" void kernel_launch(void* const* d_in, const int* in_sizes, int n_in,
                              void* d_out, int out_size)
{
    (void)in_sizes; (void)n_in; (void)out_size;
    const float* x  = (const float*)d_in[0];
    const float* Wq = (const float*)d_in[1];
    const float* Wk = (const float*)d_in[2];
    const float* Wv = (const float*)d_in[3];
    float* out = (float*)d_out;

    proj_kernel<<<(BB * TT) / 64, 256>>>(x, Wq, Wk, Wv);

    dim3 g(TT / 64, BB);
    attn_kernel<<<g, 128>>>(out);
}

// round 3
// speedup vs baseline: 1.1353x; 1.1353x over previous
#include <cuda_runtime.h>

#define BB 16
#define TT 2048
#define DD 1024
#define HH 64

// Scratch for q, k, v projections: [B*T, H] each, fp32.
__device__ float g_q[BB * TT * HH];
__device__ float g_k[BB * TT * HH];
__device__ float g_v[BB * TT * HH];

// ---------------------------------------------------------------------------
// Kernel 1: fused projection. q/k/v = x @ Wq/Wk/Wv.
// ---------------------------------------------------------------------------
__global__ __launch_bounds__(256) void proj_kernel(
    const float* __restrict__ x,
    const float* __restrict__ Wq,
    const float* __restrict__ Wk,
    const float* __restrict__ Wv)
{
    __shared__ float xs[64][36];
    __shared__ float ws[3][32][64];

    const int tid = threadIdx.x;
    const int tx = tid & 15;
    const int ty = tid >> 4;
    const int row0 = blockIdx.x * 64;

    float acc[3][4][4];
#pragma unroll
    for (int m = 0; m < 3; m++)
#pragma unroll
        for (int i = 0; i < 4; i++)
#pragma unroll
            for (int j = 0; j < 4; j++) acc[m][i][j] = 0.f;

    const float* const Wm[3] = {Wq, Wk, Wv};

    for (int k0 = 0; k0 < DD; k0 += 32) {
        {
            const int r  = tid >> 3;
            const int c4 = (tid & 7) * 4;
            *(float4*)&xs[r][c4] =
                *(const float4*)&x[(size_t)(row0 + r) * DD + k0 + c4];
            *(float4*)&xs[r + 32][c4] =
                *(const float4*)&x[(size_t)(row0 + r + 32) * DD + k0 + c4];
        }
        {
            const int r  = tid >> 4;
            const int c4 = (tid & 15) * 4;
#pragma unroll
            for (int m = 0; m < 3; m++) {
                *(float4*)&ws[m][r][c4] =
                    *(const float4*)&Wm[m][(size_t)(k0 + r) * HH + c4];
                *(float4*)&ws[m][r + 16][c4] =
                    *(const float4*)&Wm[m][(size_t)(k0 + r + 16) * HH + c4];
            }
        }
        __syncthreads();

#pragma unroll
        for (int kk = 0; kk < 32; kk++) {
            float a[4];
#pragma unroll
            for (int i = 0; i < 4; i++) a[i] = xs[ty * 4 + i][kk];
            float4 bq = *(const float4*)&ws[0][kk][tx * 4];
            float4 bk = *(const float4*)&ws[1][kk][tx * 4];
            float4 bv = *(const float4*)&ws[2][kk][tx * 4];
#pragma unroll
            for (int i = 0; i < 4; i++) {
                acc[0][i][0] += a[i] * bq.x;  acc[0][i][1] += a[i] * bq.y;
                acc[0][i][2] += a[i] * bq.z;  acc[0][i][3] += a[i] * bq.w;
                acc[1][i][0] += a[i] * bk.x;  acc[1][i][1] += a[i] * bk.y;
                acc[1][i][2] += a[i] * bk.z;  acc[1][i][3] += a[i] * bk.w;
                acc[2][i][0] += a[i] * bv.x;  acc[2][i][1] += a[i] * bv.y;
                acc[2][i][2] += a[i] * bv.z;  acc[2][i][3] += a[i] * bv.w;
            }
        }
        __syncthreads();
    }

#pragma unroll
    for (int i = 0; i < 4; i++) {
        const size_t off = (size_t)(row0 + ty * 4 + i) * HH + tx * 4;
        float4 t;
        t.x = acc[0][i][0]; t.y = acc[0][i][1]; t.z = acc[0][i][2]; t.w = acc[0][i][3];
        *(float4*)&g_q[off] = t;
        t.x = acc[1][i][0]; t.y = acc[1][i][1]; t.z = acc[1][i][2]; t.w = acc[1][i][3];
        *(float4*)&g_k[off] = t;
        t.x = acc[2][i][0]; t.y = acc[2][i][1]; t.z = acc[2][i][2]; t.w = acc[2][i][3];
        *(float4*)&g_v[off] = t;
    }
}

// ---------------------------------------------------------------------------
// Kernel 2: register-tiled causal flash attention, fp32.
// Block = 256 threads = 16(ty) x 16(tx). 128x128 S tiles, 8x8 per thread.
// P via smem for PV GEMM (8x4 O tiles). Row stats redundant in registers,
// reduced with 16-lane butterfly shuffles. Blocks pair tiles {p, 15-p} so
// every block does exactly 17 key tiles (128 blocks, 1/SM).
// ---------------------------------------------------------------------------
#define PSS 132   // Ps row stride (floats)

__global__ __launch_bounds__(256, 1) void attn_kernel(float* __restrict__ out)
{
    extern __shared__ float sm[];
    float* Qs = sm;                 // [128][64]
    float* Ks = sm + 8192;          // [128][64], chunk d4 stored at (d4 ^ (r&15))
    float* Vs = sm + 16384;         // [128][64]
    float* Ps = sm + 24576;         // [128][PSS]

    const int tid = threadIdx.x;
    const int tx  = tid & 15;
    const int ty  = tid >> 4;
    const int b   = blockIdx.y;
    const int pair = blockIdx.x;

#pragma unroll 1
    for (int half = 0; half < 2; half++) {
        const int qt = half ? (15 - pair) : pair;
        const int q0 = qt * 128;

        // Load Q tile (pre-scaled by 1/sqrt(H))
        {
            const float* qp = g_q + ((size_t)b * TT + q0) * HH;
#pragma unroll
            for (int t = 0; t < 8; t++) {
                const int idx = tid + t * 256;       // 2048 float4 slots
                const int r  = idx >> 4;
                const int c4 = (idx & 15) << 2;
                float4 v = *(const float4*)&qp[r * HH + c4];
                v.x *= 0.125f; v.y *= 0.125f; v.z *= 0.125f; v.w *= 0.125f;
                *(float4*)&Qs[r * 64 + c4] = v;
            }
        }

        float o[8][4];
        float m[8], l[8];
#pragma unroll
        for (int i = 0; i < 8; i++) {
            m[i] = -1e30f; l[i] = 0.f;
#pragma unroll
            for (int c = 0; c < 4; c++) o[i][c] = 0.f;
        }
        __syncthreads();

#pragma unroll 1
        for (int kt = 0; kt <= qt; kt++) {
            const float* kp = g_k + ((size_t)b * TT + kt * 128) * HH;
            const float* vp = g_v + ((size_t)b * TT + kt * 128) * HH;

            // Load K (swizzled chunks) and V
#pragma unroll
            for (int t = 0; t < 8; t++) {
                const int idx = tid + t * 256;
                const int r  = idx >> 4;
                const int ck = idx & 15;             // chunk index 0..15
                float4 kv = *(const float4*)&kp[r * HH + ck * 4];
                *(float4*)&Ks[r * 64 + ((ck ^ (r & 15)) << 2)] = kv;
                float4 vv = *(const float4*)&vp[r * HH + ck * 4];
                *(float4*)&Vs[r * 64 + ck * 4] = vv;
            }
            __syncthreads();

            // ---- S = Q K^T (8x8 per thread; cols c = tx + 16*jj) ----
            float s[8][8];
#pragma unroll
            for (int i = 0; i < 8; i++)
#pragma unroll
                for (int j = 0; j < 8; j++) s[i][j] = 0.f;

#pragma unroll
            for (int d4 = 0; d4 < 16; d4++) {
                float4 qa[8];
#pragma unroll
                for (int i = 0; i < 8; i++)
                    qa[i] = *(const float4*)&Qs[(ty * 8 + i) * 64 + d4 * 4];
                const int swz = (d4 ^ tx) << 2;      // (c & 15) == tx for our cols
#pragma unroll
                for (int jj = 0; jj < 8; jj++) {
                    const int c = tx + 16 * jj;
                    float4 kb = *(const float4*)&Ks[c * 64 + swz];
#pragma unroll
                    for (int i = 0; i < 8; i++) {
                        s[i][jj] += qa[i].x * kb.x + qa[i].y * kb.y
                                  + qa[i].z * kb.z + qa[i].w * kb.w;
                    }
                }
            }

            // ---- causal mask (diagonal tile only) ----
            if (kt == qt) {
#pragma unroll
                for (int i = 0; i < 8; i++) {
                    const int r = ty * 8 + i;
#pragma unroll
                    for (int jj = 0; jj < 8; jj++) {
                        if (tx + 16 * jj > r) s[i][jj] = -1e30f;
                    }
                }
            }

            // ---- online softmax (row = 16 lanes of same ty) ----
#pragma unroll
            for (int i = 0; i < 8; i++) {
                float mx = s[i][0];
#pragma unroll
                for (int jj = 1; jj < 8; jj++) mx = fmaxf(mx, s[i][jj]);
#pragma unroll
                for (int off = 8; off > 0; off >>= 1)
                    mx = fmaxf(mx, __shfl_xor_sync(0xffffffffu, mx, off));
                mx = fmaxf(mx, m[i]);

                const float alpha = __expf(m[i] - mx);
                m[i] = mx;

                float rs = 0.f;
#pragma unroll
                for (int jj = 0; jj < 8; jj++) {
                    const float p = __expf(s[i][jj] - mx);
                    s[i][jj] = p;
                    rs += p;
                }
#pragma unroll
                for (int off = 8; off > 0; off >>= 1)
                    rs += __shfl_xor_sync(0xffffffffu, rs, off);
                l[i] = l[i] * alpha + rs;

#pragma unroll
                for (int c = 0; c < 4; c++) o[i][c] *= alpha;

#pragma unroll
                for (int jj = 0; jj < 8; jj++)
                    Ps[(ty * 8 + i) * PSS + tx + 16 * jj] = s[i][jj];
            }
            __syncthreads();

            // ---- O += P V (8 rows x 4 cols per thread) ----
#pragma unroll
            for (int j4 = 0; j4 < 32; j4++) {
                float4 pv[8];
#pragma unroll
                for (int i = 0; i < 8; i++)
                    pv[i] = *(const float4*)&Ps[(ty * 8 + i) * PSS + j4 * 4];
#pragma unroll
                for (int dj = 0; dj < 4; dj++) {
                    const float4 vv = *(const float4*)&Vs[(j4 * 4 + dj) * 64 + tx * 4];
#pragma unroll
                    for (int i = 0; i < 8; i++) {
                        const float p = ((const float*)&pv[i])[dj];
                        o[i][0] += p * vv.x;
                        o[i][1] += p * vv.y;
                        o[i][2] += p * vv.z;
                        o[i][3] += p * vv.w;
                    }
                }
            }
            __syncthreads();
        }

        // ---- epilogue ----
#pragma unroll
        for (int i = 0; i < 8; i++) {
            const float inv = 1.f / l[i];
            float4 t;
            t.x = o[i][0] * inv; t.y = o[i][1] * inv;
            t.z = o[i][2] * inv; t.w = o[i][3] * inv;
            *(float4*)&out[((size_t)b * TT + q0 + ty * 8 + i) * HH + tx * 4] = t;
        }
        __syncthreads();
    }
}

// ---------------------------------------------------------------------------
extern "C" void kernel_launch(void* const* d_in, const int* in_sizes, int n_in,
                              void* d_out, int out_size)
{
    (void)in_sizes; (void)n_in; (void)out_size;
    const float* x  = (const float*)d_in[0];
    const float* Wq = (const float*)d_in[1];
    const float* Wk = (const float*)d_in[2];
    const float* Wv = (const float*)d_in[3];
    float* out = (float*)d_out;

    proj_kernel<<<(BB * TT) / 64, 256>>>(x, Wq, Wk, Wv);

    const int smem_bytes = (24576 + 128 * PSS) * 4;   // 165,888 B
    cudaFuncSetAttribute(attn_kernel,
                         cudaFuncAttributeMaxDynamicSharedMemorySize, smem_bytes);
    dim3 g(8, BB);
    attn_kernel<<<g, 256, smem_bytes>>>(out);
}

// round 4
// speedup vs baseline: 1.8456x; 1.6257x over previous
#include <cuda_runtime.h>

#define BB 16
#define TT 2048
#define DD 1024
#define HH 64

// Scratch for q, k, v projections: [B*T, H] each, fp32.
__device__ float g_q[BB * TT * HH];
__device__ float g_k[BB * TT * HH];
__device__ float g_v[BB * TT * HH];

// ---------------------------------------------------------------------------
// Kernel 1: fused projection. q/k/v = x @ Wq/Wk/Wv.  (unchanged)
// ---------------------------------------------------------------------------
__global__ __launch_bounds__(256) void proj_kernel(
    const float* __restrict__ x,
    const float* __restrict__ Wq,
    const float* __restrict__ Wk,
    const float* __restrict__ Wv)
{
    __shared__ float xs[64][36];
    __shared__ float ws[3][32][64];

    const int tid = threadIdx.x;
    const int tx = tid & 15;
    const int ty = tid >> 4;
    const int row0 = blockIdx.x * 64;

    float acc[3][4][4];
#pragma unroll
    for (int m = 0; m < 3; m++)
#pragma unroll
        for (int i = 0; i < 4; i++)
#pragma unroll
            for (int j = 0; j < 4; j++) acc[m][i][j] = 0.f;

    const float* const Wm[3] = {Wq, Wk, Wv};

    for (int k0 = 0; k0 < DD; k0 += 32) {
        {
            const int r  = tid >> 3;
            const int c4 = (tid & 7) * 4;
            *(float4*)&xs[r][c4] =
                *(const float4*)&x[(size_t)(row0 + r) * DD + k0 + c4];
            *(float4*)&xs[r + 32][c4] =
                *(const float4*)&x[(size_t)(row0 + r + 32) * DD + k0 + c4];
        }
        {
            const int r  = tid >> 4;
            const int c4 = (tid & 15) * 4;
#pragma unroll
            for (int m = 0; m < 3; m++) {
                *(float4*)&ws[m][r][c4] =
                    *(const float4*)&Wm[m][(size_t)(k0 + r) * HH + c4];
                *(float4*)&ws[m][r + 16][c4] =
                    *(const float4*)&Wm[m][(size_t)(k0 + r + 16) * HH + c4];
            }
        }
        __syncthreads();

#pragma unroll
        for (int kk = 0; kk < 32; kk++) {
            float a[4];
#pragma unroll
            for (int i = 0; i < 4; i++) a[i] = xs[ty * 4 + i][kk];
            float4 bq = *(const float4*)&ws[0][kk][tx * 4];
            float4 bk = *(const float4*)&ws[1][kk][tx * 4];
            float4 bv = *(const float4*)&ws[2][kk][tx * 4];
#pragma unroll
            for (int i = 0; i < 4; i++) {
                acc[0][i][0] += a[i] * bq.x;  acc[0][i][1] += a[i] * bq.y;
                acc[0][i][2] += a[i] * bq.z;  acc[0][i][3] += a[i] * bq.w;
                acc[1][i][0] += a[i] * bk.x;  acc[1][i][1] += a[i] * bk.y;
                acc[1][i][2] += a[i] * bk.z;  acc[1][i][3] += a[i] * bk.w;
                acc[2][i][0] += a[i] * bv.x;  acc[2][i][1] += a[i] * bv.y;
                acc[2][i][2] += a[i] * bv.z;  acc[2][i][3] += a[i] * bv.w;
            }
        }
        __syncthreads();
    }

#pragma unroll
    for (int i = 0; i < 4; i++) {
        const size_t off = (size_t)(row0 + ty * 4 + i) * HH + tx * 4;
        float4 t;
        t.x = acc[0][i][0]; t.y = acc[0][i][1]; t.z = acc[0][i][2]; t.w = acc[0][i][3];
        *(float4*)&g_q[off] = t;
        t.x = acc[1][i][0]; t.y = acc[1][i][1]; t.z = acc[1][i][2]; t.w = acc[1][i][3];
        *(float4*)&g_k[off] = t;
        t.x = acc[2][i][0]; t.y = acc[2][i][1]; t.z = acc[2][i][2]; t.w = acc[2][i][3];
        *(float4*)&g_v[off] = t;
    }
}

// ---------------------------------------------------------------------------
// Kernel 2: register-tiled causal flash attention, fp32.
// Block = 512 threads = 32(ty) x 16(tx). 128x128 S tiles, 4x8 per thread
// (rows ty*4+i, cols tx+16*jj). P via smem for the PV GEMM (4x4 O tiles).
// Row stats redundant across the 16 lanes of a row, reduced with 16-lane
// butterfly shuffles. Blocks pair query tiles {p, 15-p}: every block does
// exactly 17 key tiles. 128 blocks, 1 per SM, 16 warps each.
// ---------------------------------------------------------------------------
#define PSS 132   // Ps row stride (floats)

__global__ __launch_bounds__(512, 1) void attn_kernel(float* __restrict__ out)
{
    extern __shared__ float sm[];
    float* Qs = sm;                 // [128][64]
    float* Ks = sm + 8192;          // [128][64], chunk d4 stored at (d4 ^ (r&15))
    float* Vs = sm + 16384;         // [128][64]
    float* Ps = sm + 24576;         // [128][PSS]

    const int tid = threadIdx.x;
    const int tx  = tid & 15;
    const int ty  = tid >> 4;       // 0..31 -> rows ty*4 .. ty*4+3
    const int b   = blockIdx.y;
    const int pair = blockIdx.x;

#pragma unroll 1
    for (int half = 0; half < 2; half++) {
        const int qt = half ? (15 - pair) : pair;
        const int q0 = qt * 128;

        // Load Q tile (pre-scaled by 1/sqrt(H))
        {
            const float* qp = g_q + ((size_t)b * TT + q0) * HH;
#pragma unroll
            for (int t = 0; t < 4; t++) {
                const int idx = tid + t * 512;       // 2048 float4 slots
                const int r  = idx >> 4;
                const int c4 = (idx & 15) << 2;
                float4 v = *(const float4*)&qp[r * HH + c4];
                v.x *= 0.125f; v.y *= 0.125f; v.z *= 0.125f; v.w *= 0.125f;
                *(float4*)&Qs[r * 64 + c4] = v;
            }
        }

        float o[4][4];
        float m[4], l[4];
#pragma unroll
        for (int i = 0; i < 4; i++) {
            m[i] = -1e30f; l[i] = 0.f;
#pragma unroll
            for (int c = 0; c < 4; c++) o[i][c] = 0.f;
        }
        __syncthreads();

#pragma unroll 1
        for (int kt = 0; kt <= qt; kt++) {
            const float* kp = g_k + ((size_t)b * TT + kt * 128) * HH;
            const float* vp = g_v + ((size_t)b * TT + kt * 128) * HH;

            // Load K (swizzled chunks) and V
#pragma unroll
            for (int t = 0; t < 4; t++) {
                const int idx = tid + t * 512;
                const int r  = idx >> 4;
                const int ck = idx & 15;
                float4 kv = *(const float4*)&kp[r * HH + ck * 4];
                *(float4*)&Ks[r * 64 + ((ck ^ (r & 15)) << 2)] = kv;
                float4 vv = *(const float4*)&vp[r * HH + ck * 4];
                *(float4*)&Vs[r * 64 + ck * 4] = vv;
            }
            __syncthreads();

            // ---- S = Q K^T (4x8 per thread; cols c = tx + 16*jj) ----
            float s[4][8];
#pragma unroll
            for (int i = 0; i < 4; i++)
#pragma unroll
                for (int j = 0; j < 8; j++) s[i][j] = 0.f;

#pragma unroll
            for (int d4 = 0; d4 < 16; d4++) {
                float4 qa[4];
#pragma unroll
                for (int i = 0; i < 4; i++)
                    qa[i] = *(const float4*)&Qs[(ty * 4 + i) * 64 + d4 * 4];
                const int swz = (d4 ^ tx) << 2;      // (c & 15) == tx for our cols
#pragma unroll
                for (int jj = 0; jj < 8; jj++) {
                    const int c = tx + 16 * jj;
                    float4 kb = *(const float4*)&Ks[c * 64 + swz];
#pragma unroll
                    for (int i = 0; i < 4; i++) {
                        s[i][jj] += qa[i].x * kb.x + qa[i].y * kb.y
                                  + qa[i].z * kb.z + qa[i].w * kb.w;
                    }
                }
            }

            // ---- causal mask (diagonal tile only) ----
            if (kt == qt) {
#pragma unroll
                for (int i = 0; i < 4; i++) {
                    const int r = ty * 4 + i;
#pragma unroll
                    for (int jj = 0; jj < 8; jj++) {
                        if (tx + 16 * jj > r) s[i][jj] = -1e30f;
                    }
                }
            }

            // ---- online softmax (row = 16 lanes of same ty) ----
#pragma unroll
            for (int i = 0; i < 4; i++) {
                float mx = s[i][0];
#pragma unroll
                for (int jj = 1; jj < 8; jj++) mx = fmaxf(mx, s[i][jj]);
#pragma unroll
                for (int off = 8; off > 0; off >>= 1)
                    mx = fmaxf(mx, __shfl_xor_sync(0xffffffffu, mx, off));
                mx = fmaxf(mx, m[i]);

                const float alpha = __expf(m[i] - mx);
                m[i] = mx;

                float rs = 0.f;
#pragma unroll
                for (int jj = 0; jj < 8; jj++) {
                    const float p = __expf(s[i][jj] - mx);
                    s[i][jj] = p;
                    rs += p;
                }
#pragma unroll
                for (int off = 8; off > 0; off >>= 1)
                    rs += __shfl_xor_sync(0xffffffffu, rs, off);
                l[i] = l[i] * alpha + rs;

#pragma unroll
                for (int c = 0; c < 4; c++) o[i][c] *= alpha;

#pragma unroll
                for (int jj = 0; jj < 8; jj++)
                    Ps[(ty * 4 + i) * PSS + tx + 16 * jj] = s[i][jj];
            }
            __syncthreads();

            // ---- O += P V (4 rows x 4 cols per thread) ----
#pragma unroll
            for (int j4 = 0; j4 < 32; j4++) {
                float4 pv[4];
#pragma unroll
                for (int i = 0; i < 4; i++)
                    pv[i] = *(const float4*)&Ps[(ty * 4 + i) * PSS + j4 * 4];
#pragma unroll
                for (int dj = 0; dj < 4; dj++) {
                    const float4 vv = *(const float4*)&Vs[(j4 * 4 + dj) * 64 + tx * 4];
#pragma unroll
                    for (int i = 0; i < 4; i++) {
                        const float p = ((const float*)&pv[i])[dj];
                        o[i][0] += p * vv.x;
                        o[i][1] += p * vv.y;
                        o[i][2] += p * vv.z;
                        o[i][3] += p * vv.w;
                    }
                }
            }
            __syncthreads();
        }

        // ---- epilogue ----
#pragma unroll
        for (int i = 0; i < 4; i++) {
            const float inv = 1.f / l[i];
            float4 t;
            t.x = o[i][0] * inv; t.y = o[i][1] * inv;
            t.z = o[i][2] * inv; t.w = o[i][3] * inv;
            *(float4*)&out[((size_t)b * TT + q0 + ty * 4 + i) * HH + tx * 4] = t;
        }
        __syncthreads();
    }
}

// ---------------------------------------------------------------------------
extern "C" void kernel_launch(void* const* d_in, const int* in_sizes, int n_in,
                              void* d_out, int out_size)
{
    (void)in_sizes; (void)n_in; (void)out_size;
    const float* x  = (const float*)d_in[0];
    const float* Wq = (const float*)d_in[1];
    const float* Wk = (const float*)d_in[2];
    const float* Wv = (const float*)d_in[3];
    float* out = (float*)d_out;

    proj_kernel<<<(BB * TT) / 64, 256>>>(x, Wq, Wk, Wv);

    const int smem_bytes = (24576 + 128 * PSS) * 4;   // 165,888 B
    cudaFuncSetAttribute(attn_kernel,
                         cudaFuncAttributeMaxDynamicSharedMemorySize, smem_bytes);
    dim3 g(8, BB);
    attn_kernel<<<g, 512, smem_bytes>>>(out);
}

// round 6
// speedup vs baseline: 3.0164x; 1.6343x over previous
#include <cuda_runtime.h>
#include <cstdint>

#define BB 16
#define TT 2048
#define DD 1024
#define HH 64

// Scratch: q/k/v projections [B*T, H] fp32, and K-major tf32 weights.
__device__ float g_q[BB * TT * HH];
__device__ float g_k[BB * TT * HH];
__device__ float g_v[BB * TT * HH];
__device__ float g_wt[3 * HH * DD];   // Wt[(m*64+n)][k] = tf32(W_m[k][n]), K-major

__device__ __forceinline__ uint32_t f32_to_tf32(float f) {
    uint32_t u;
    asm("cvt.rna.tf32.f32 %0, %1;" : "=r"(u) : "f"(f));
    return u;
}

__device__ __forceinline__ void mma_tf32(float d[4], const uint32_t a[4],
                                         const uint32_t b[2]) {
    asm volatile(
        "mma.sync.aligned.m16n8k8.row.col.f32.tf32.tf32.f32 "
        "{%0,%1,%2,%3}, {%4,%5,%6,%7}, {%8,%9}, {%0,%1,%2,%3};"
        : "+f"(d[0]), "+f"(d[1]), "+f"(d[2]), "+f"(d[3])
        : "r"(a[0]), "r"(a[1]), "r"(a[2]), "r"(a[3]), "r"(b[0]), "r"(b[1]));
}

// ===========================================================================
// Kernel 0: W -> Wt[(m*64+n)][k], tf32-rounded, K-major.
// ===========================================================================
__global__ void wt_kernel(const float* __restrict__ Wq,
                          const float* __restrict__ Wk,
                          const float* __restrict__ Wv)
{
    const int idx = blockIdx.x * 256 + threadIdx.x;     // 0 .. 3*64*1024-1
    const int m = idx >> 16;
    const int n = (idx >> 10) & 63;
    const int k = idx & 1023;
    const float* W = (m == 0) ? Wq : (m == 1) ? Wk : Wv;
    ((uint32_t*)g_wt)[idx] = f32_to_tf32(W[k * HH + n]);
}

// ===========================================================================
// Kernel 1: tf32 mma.sync projection.
// CTA: 128 rows x 192 cols (q|k|v). 256 threads = 2 warp-rows x 4 warp-cols.
// Warp tile 64x48 = 4 m-tiles x 6 n-tiles of m16n8k8. K chunk = 32.
// smem rows use stride 36 floats: fragment scalar LDS bank == lane (CF),
// and float4 STS are conflict-free. Register prefetch hides gmem latency.
// ===========================================================================
#define AST 36
__global__ __launch_bounds__(256) void proj_mma_kernel(const float* __restrict__ x)
{
    __shared__ float As[128 * AST];    // 18,432 B
    __shared__ float Bs[192 * AST];    // 27,648 B

    const int tid  = threadIdx.x;
    const int warp = tid >> 5;
    const int lane = tid & 31;
    const int wr   = warp >> 2;        // 0..1 -> rows wr*64 ..
    const int wc   = warp & 3;         // 0..3 -> cols wc*48 ..
    const int row0 = blockIdx.x * 128;

    float d[4][6][4];
#pragma unroll
    for (int mt = 0; mt < 4; mt++)
#pragma unroll
        for (int nt = 0; nt < 6; nt++)
#pragma unroll
            for (int r = 0; r < 4; r++) d[mt][nt][r] = 0.f;

    // prefetch registers
    float4 aP[4];
    uint4  bP[6];

    // ---- prefetch chunk 0 ----
#pragma unroll
    for (int t = 0; t < 4; t++) {
        const int idx = tid + t * 256;           // 0..1023
        const int r  = idx >> 3, c4 = (idx & 7) * 4;
        aP[t] = *(const float4*)&x[(size_t)(row0 + r) * DD + c4];
    }
#pragma unroll
    for (int t = 0; t < 6; t++) {
        const int idx = tid + t * 256;           // 0..1535
        const int n = idx >> 3, c4 = (idx & 7) * 4;
        bP[t] = *(const uint4*)&g_wt[n * DD + c4];
    }

#pragma unroll 1
    for (int chunk = 0; chunk < 32; chunk++) {
        // ---- store prefetched chunk to smem ----
#pragma unroll
        for (int t = 0; t < 4; t++) {
            const int idx = tid + t * 256;
            const int r  = idx >> 3, c4 = (idx & 7) * 4;
            uint4 u;
            u.x = f32_to_tf32(aP[t].x); u.y = f32_to_tf32(aP[t].y);
            u.z = f32_to_tf32(aP[t].z); u.w = f32_to_tf32(aP[t].w);
            *(uint4*)&As[r * AST + c4] = u;
        }
#pragma unroll
        for (int t = 0; t < 6; t++) {
            const int idx = tid + t * 256;
            const int n = idx >> 3, c4 = (idx & 7) * 4;
            *(uint4*)&Bs[n * AST + c4] = bP[t];
        }
        __syncthreads();

        // ---- issue gmem loads for next chunk (overlap with compute) ----
        if (chunk < 31) {
            const int kc = (chunk + 1) * 32;
#pragma unroll
            for (int t = 0; t < 4; t++) {
                const int idx = tid + t * 256;
                const int r  = idx >> 3, c4 = (idx & 7) * 4;
                aP[t] = *(const float4*)&x[(size_t)(row0 + r) * DD + kc + c4];
            }
#pragma unroll
            for (int t = 0; t < 6; t++) {
                const int idx = tid + t * 256;
                const int n = idx >> 3, c4 = (idx & 7) * 4;
                bP[t] = *(const uint4*)&g_wt[n * DD + kc + c4];
            }
        }

        // ---- compute: 4 k-steps of m16n8k8 ----
#pragma unroll
        for (int ks = 0; ks < 4; ks++) {
            const int k0 = ks * 8;
            uint32_t a[4][4];
#pragma unroll
            for (int mt = 0; mt < 4; mt++) {
                const int base = (wr * 64 + mt * 16 + (lane >> 2)) * AST
                               + k0 + (lane & 3);
                a[mt][0] = __float_as_uint(As[base]);
                a[mt][1] = __float_as_uint(As[base + 8 * AST]);
                a[mt][2] = __float_as_uint(As[base + 4]);
                a[mt][3] = __float_as_uint(As[base + 8 * AST + 4]);
            }
            uint32_t bfr[6][2];
#pragma unroll
            for (int nt = 0; nt < 6; nt++) {
                const int base = (wc * 48 + nt * 8 + (lane >> 2)) * AST
                               + k0 + (lane & 3);
                bfr[nt][0] = __float_as_uint(Bs[base]);
                bfr[nt][1] = __float_as_uint(Bs[base + 4]);
            }
#pragma unroll
            for (int mt = 0; mt < 4; mt++)
#pragma unroll
                for (int nt = 0; nt < 6; nt++)
                    mma_tf32(d[mt][nt], a[mt], bfr[nt]);
        }
        __syncthreads();
    }

    // ---- epilogue: write q/k/v ----
#pragma unroll
    for (int nt = 0; nt < 6; nt++) {
        const int cg = wc * 48 + nt * 8;
        const int m  = cg >> 6;
        const int c  = (cg & 63) + (lane & 3) * 2;
        float* gm = (m == 0) ? g_q : (m == 1) ? g_k : g_v;
#pragma unroll
        for (int mt = 0; mt < 4; mt++) {
            const int row = row0 + wr * 64 + mt * 16 + (lane >> 2);
            float2 t0; t0.x = d[mt][nt][0]; t0.y = d[mt][nt][1];
            *(float2*)&gm[(size_t)row * HH + c] = t0;
            float2 t1; t1.x = d[mt][nt][2]; t1.y = d[mt][nt][3];
            *(float2*)&gm[(size_t)(row + 8) * HH + c] = t1;
        }
    }
}

// ===========================================================================
// Kernel 2: register-tiled causal flash attention, fp32 (unchanged, 292us).
// ===========================================================================
#define PSS 132

__global__ __launch_bounds__(512, 1) void attn_kernel(float* __restrict__ out)
{
    extern __shared__ float sm[];
    float* Qs = sm;
    float* Ks = sm + 8192;
    float* Vs = sm + 16384;
    float* Ps = sm + 24576;

    const int tid = threadIdx.x;
    const int tx  = tid & 15;
    const int ty  = tid >> 4;
    const int b   = blockIdx.y;
    const int pair = blockIdx.x;

#pragma unroll 1
    for (int half = 0; half < 2; half++) {
        const int qt = half ? (15 - pair) : pair;
        const int q0 = qt * 128;

        {
            const float* qp = g_q + ((size_t)b * TT + q0) * HH;
#pragma unroll
            for (int t = 0; t < 4; t++) {
                const int idx = tid + t * 512;
                const int r  = idx >> 4;
                const int c4 = (idx & 15) << 2;
                float4 v = *(const float4*)&qp[r * HH + c4];
                v.x *= 0.125f; v.y *= 0.125f; v.z *= 0.125f; v.w *= 0.125f;
                *(float4*)&Qs[r * 64 + c4] = v;
            }
        }

        float o[4][4];
        float m[4], l[4];
#pragma unroll
        for (int i = 0; i < 4; i++) {
            m[i] = -1e30f; l[i] = 0.f;
#pragma unroll
            for (int c = 0; c < 4; c++) o[i][c] = 0.f;
        }
        __syncthreads();

#pragma unroll 1
        for (int kt = 0; kt <= qt; kt++) {
            const float* kp = g_k + ((size_t)b * TT + kt * 128) * HH;
            const float* vp = g_v + ((size_t)b * TT + kt * 128) * HH;

#pragma unroll
            for (int t = 0; t < 4; t++) {
                const int idx = tid + t * 512;
                const int r  = idx >> 4;
                const int ck = idx & 15;
                float4 kv = *(const float4*)&kp[r * HH + ck * 4];
                *(float4*)&Ks[r * 64 + ((ck ^ (r & 15)) << 2)] = kv;
                float4 vv = *(const float4*)&vp[r * HH + ck * 4];
                *(float4*)&Vs[r * 64 + ck * 4] = vv;
            }
            __syncthreads();

            float s[4][8];
#pragma unroll
            for (int i = 0; i < 4; i++)
#pragma unroll
                for (int j = 0; j < 8; j++) s[i][j] = 0.f;

#pragma unroll
            for (int d4 = 0; d4 < 16; d4++) {
                float4 qa[4];
#pragma unroll
                for (int i = 0; i < 4; i++)
                    qa[i] = *(const float4*)&Qs[(ty * 4 + i) * 64 + d4 * 4];
                const int swz = (d4 ^ tx) << 2;
#pragma unroll
                for (int jj = 0; jj < 8; jj++) {
                    const int c = tx + 16 * jj;
                    float4 kb = *(const float4*)&Ks[c * 64 + swz];
#pragma unroll
                    for (int i = 0; i < 4; i++) {
                        s[i][jj] += qa[i].x * kb.x + qa[i].y * kb.y
                                  + qa[i].z * kb.z + qa[i].w * kb.w;
                    }
                }
            }

            if (kt == qt) {
#pragma unroll
                for (int i = 0; i < 4; i++) {
                    const int r = ty * 4 + i;
#pragma unroll
                    for (int jj = 0; jj < 8; jj++) {
                        if (tx + 16 * jj > r) s[i][jj] = -1e30f;
                    }
                }
            }

#pragma unroll
            for (int i = 0; i < 4; i++) {
                float mx = s[i][0];
#pragma unroll
                for (int jj = 1; jj < 8; jj++) mx = fmaxf(mx, s[i][jj]);
#pragma unroll
                for (int off = 8; off > 0; off >>= 1)
                    mx = fmaxf(mx, __shfl_xor_sync(0xffffffffu, mx, off));
                mx = fmaxf(mx, m[i]);

                const float alpha = __expf(m[i] - mx);
                m[i] = mx;

                float rs = 0.f;
#pragma unroll
                for (int jj = 0; jj < 8; jj++) {
                    const float p = __expf(s[i][jj] - mx);
                    s[i][jj] = p;
                    rs += p;
                }
#pragma unroll
                for (int off = 8; off > 0; off >>= 1)
                    rs += __shfl_xor_sync(0xffffffffu, rs, off);
                l[i] = l[i] * alpha + rs;

#pragma unroll
                for (int c = 0; c < 4; c++) o[i][c] *= alpha;

#pragma unroll
                for (int jj = 0; jj < 8; jj++)
                    Ps[(ty * 4 + i) * PSS + tx + 16 * jj] = s[i][jj];
            }
            __syncthreads();

#pragma unroll
            for (int j4 = 0; j4 < 32; j4++) {
                float4 pv[4];
#pragma unroll
                for (int i = 0; i < 4; i++)
                    pv[i] = *(const float4*)&Ps[(ty * 4 + i) * PSS + j4 * 4];
#pragma unroll
                for (int dj = 0; dj < 4; dj++) {
                    const float4 vv = *(const float4*)&Vs[(j4 * 4 + dj) * 64 + tx * 4];
#pragma unroll
                    for (int i = 0; i < 4; i++) {
                        const float p = ((const float*)&pv[i])[dj];
                        o[i][0] += p * vv.x;
                        o[i][1] += p * vv.y;
                        o[i][2] += p * vv.z;
                        o[i][3] += p * vv.w;
                    }
                }
            }
            __syncthreads();
        }

#pragma unroll
        for (int i = 0; i < 4; i++) {
            const float inv = 1.f / l[i];
            float4 t;
            t.x = o[i][0] * inv; t.y = o[i][1] * inv;
            t.z = o[i][2] * inv; t.w = o[i][3] * inv;
            *(float4*)&out[((size_t)b * TT + q0 + ty * 4 + i) * HH + tx * 4] = t;
        }
        __syncthreads();
    }
}

// ===========================================================================
extern "C" void kernel_launch(void* const* d_in, const int* in_sizes, int n_in,
                              void* d_out, int out_size)
{
    (void)in_sizes; (void)n_in; (void)out_size;
    const float* x  = (const float*)d_in[0];
    const float* Wq = (const float*)d_in[1];
    const float* Wk = (const float*)d_in[2];
    const float* Wv = (const float*)d_in[3];
    float* out = (float*)d_out;

    wt_kernel<<<(3 * HH * DD) / 256, 256>>>(Wq, Wk, Wv);

    proj_mma_kernel<<<(BB * TT) / 128, 256>>>(x);

    const int attn_smem = (24576 + 128 * PSS) * 4;
    cudaFuncSetAttribute(attn_kernel,
                         cudaFuncAttributeMaxDynamicSharedMemorySize, attn_smem);
    dim3 g(8, BB);
    attn_kernel<<<g, 512, attn_smem>>>(out);
}

// round 7
// speedup vs baseline: 5.7963x; 1.9216x over previous
#include <cuda_runtime.h>
#include <cstdint>

#define BB 16
#define TT 2048
#define DD 1024
#define HH 64

// Scratch: q/k/v projections [B*T, H] fp32, and K-major tf32 weights.
__device__ float g_q[BB * TT * HH];
__device__ float g_k[BB * TT * HH];
__device__ float g_v[BB * TT * HH];
__device__ float g_wt[3 * HH * DD];   // Wt[(m*64+n)][k] = tf32(W_m[k][n]), K-major

__device__ __forceinline__ uint32_t f32_to_tf32(float f) {
    uint32_t u;
    asm("cvt.rna.tf32.f32 %0, %1;" : "=r"(u) : "f"(f));
    return u;
}

__device__ __forceinline__ void mma_tf32(float d[4], const uint32_t a[4],
                                         const uint32_t b[2]) {
    asm volatile(
        "mma.sync.aligned.m16n8k8.row.col.f32.tf32.tf32.f32 "
        "{%0,%1,%2,%3}, {%4,%5,%6,%7}, {%8,%9}, {%0,%1,%2,%3};"
        : "+f"(d[0]), "+f"(d[1]), "+f"(d[2]), "+f"(d[3])
        : "r"(a[0]), "r"(a[1]), "r"(a[2]), "r"(a[3]), "r"(b[0]), "r"(b[1]));
}

// ===========================================================================
// Kernel 0: W -> Wt[(m*64+n)][k], tf32-rounded, K-major.
// ===========================================================================
__global__ void wt_kernel(const float* __restrict__ Wq,
                          const float* __restrict__ Wk,
                          const float* __restrict__ Wv)
{
    const int idx = blockIdx.x * 256 + threadIdx.x;
    const int m = idx >> 16;
    const int n = (idx >> 10) & 63;
    const int k = idx & 1023;
    const float* W = (m == 0) ? Wq : (m == 1) ? Wk : Wv;
    ((uint32_t*)g_wt)[idx] = f32_to_tf32(W[k * HH + n]);
}

// ===========================================================================
// Kernel 1: tf32 mma.sync projection (unchanged from R6, ~76us).
// ===========================================================================
#define AST 36
__global__ __launch_bounds__(256) void proj_mma_kernel(const float* __restrict__ x)
{
    __shared__ float As[128 * AST];
    __shared__ float Bs[192 * AST];

    const int tid  = threadIdx.x;
    const int warp = tid >> 5;
    const int lane = tid & 31;
    const int wr   = warp >> 2;
    const int wc   = warp & 3;
    const int row0 = blockIdx.x * 128;

    float d[4][6][4];
#pragma unroll
    for (int mt = 0; mt < 4; mt++)
#pragma unroll
        for (int nt = 0; nt < 6; nt++)
#pragma unroll
            for (int r = 0; r < 4; r++) d[mt][nt][r] = 0.f;

    float4 aP[4];
    uint4  bP[6];

#pragma unroll
    for (int t = 0; t < 4; t++) {
        const int idx = tid + t * 256;
        const int r  = idx >> 3, c4 = (idx & 7) * 4;
        aP[t] = *(const float4*)&x[(size_t)(row0 + r) * DD + c4];
    }
#pragma unroll
    for (int t = 0; t < 6; t++) {
        const int idx = tid + t * 256;
        const int n = idx >> 3, c4 = (idx & 7) * 4;
        bP[t] = *(const uint4*)&g_wt[n * DD + c4];
    }

#pragma unroll 1
    for (int chunk = 0; chunk < 32; chunk++) {
#pragma unroll
        for (int t = 0; t < 4; t++) {
            const int idx = tid + t * 256;
            const int r  = idx >> 3, c4 = (idx & 7) * 4;
            uint4 u;
            u.x = f32_to_tf32(aP[t].x); u.y = f32_to_tf32(aP[t].y);
            u.z = f32_to_tf32(aP[t].z); u.w = f32_to_tf32(aP[t].w);
            *(uint4*)&As[r * AST + c4] = u;
        }
#pragma unroll
        for (int t = 0; t < 6; t++) {
            const int idx = tid + t * 256;
            const int n = idx >> 3, c4 = (idx & 7) * 4;
            *(uint4*)&Bs[n * AST + c4] = bP[t];
        }
        __syncthreads();

        if (chunk < 31) {
            const int kc = (chunk + 1) * 32;
#pragma unroll
            for (int t = 0; t < 4; t++) {
                const int idx = tid + t * 256;
                const int r  = idx >> 3, c4 = (idx & 7) * 4;
                aP[t] = *(const float4*)&x[(size_t)(row0 + r) * DD + kc + c4];
            }
#pragma unroll
            for (int t = 0; t < 6; t++) {
                const int idx = tid + t * 256;
                const int n = idx >> 3, c4 = (idx & 7) * 4;
                bP[t] = *(const uint4*)&g_wt[n * DD + kc + c4];
            }
        }

#pragma unroll
        for (int ks = 0; ks < 4; ks++) {
            const int k0 = ks * 8;
            uint32_t a[4][4];
#pragma unroll
            for (int mt = 0; mt < 4; mt++) {
                const int base = (wr * 64 + mt * 16 + (lane >> 2)) * AST
                               + k0 + (lane & 3);
                a[mt][0] = __float_as_uint(As[base]);
                a[mt][1] = __float_as_uint(As[base + 8 * AST]);
                a[mt][2] = __float_as_uint(As[base + 4]);
                a[mt][3] = __float_as_uint(As[base + 8 * AST + 4]);
            }
            uint32_t bfr[6][2];
#pragma unroll
            for (int nt = 0; nt < 6; nt++) {
                const int base = (wc * 48 + nt * 8 + (lane >> 2)) * AST
                               + k0 + (lane & 3);
                bfr[nt][0] = __float_as_uint(Bs[base]);
                bfr[nt][1] = __float_as_uint(Bs[base + 4]);
            }
#pragma unroll
            for (int mt = 0; mt < 4; mt++)
#pragma unroll
                for (int nt = 0; nt < 6; nt++)
                    mma_tf32(d[mt][nt], a[mt], bfr[nt]);
        }
        __syncthreads();
    }

#pragma unroll
    for (int nt = 0; nt < 6; nt++) {
        const int cg = wc * 48 + nt * 8;
        const int m  = cg >> 6;
        const int c  = (cg & 63) + (lane & 3) * 2;
        float* gm = (m == 0) ? g_q : (m == 1) ? g_k : g_v;
#pragma unroll
        for (int mt = 0; mt < 4; mt++) {
            const int row = row0 + wr * 64 + mt * 16 + (lane >> 2);
            float2 t0; t0.x = d[mt][nt][0]; t0.y = d[mt][nt][1];
            *(float2*)&gm[(size_t)row * HH + c] = t0;
            float2 t1; t1.x = d[mt][nt][2]; t1.y = d[mt][nt][3];
            *(float2*)&gm[(size_t)(row + 8) * HH + c] = t1;
        }
    }
}

// ===========================================================================
// Kernel 2: tensor-core causal flash attention (tf32 mma.sync).
// 256 threads = 8 warps; warp w owns S/O rows [w*16, w*16+16).
// QK^T: A from Qs (st 68), B from Ks (st 68, row-major K == n-major B).
// Softmax on accumulator layout (quad shuffles). P -> Ps (st 132, warp-
// private rows, no block sync needed). PV: A from Ps, B straight from
// row-major Vs (st 72; bank = 8*(lane&3)+(lane>>2), conflict-free).
// Blocks pair q-tiles {p, 15-p}: 17 key tiles each, 128 blocks.
// ===========================================================================
#define QST 68
#define KST 68
#define VST 72
#define PST 132

__global__ __launch_bounds__(256, 1) void attn_kernel(float* __restrict__ out)
{
    extern __shared__ float sm[];
    float* Qs = sm;                              // 128*68
    float* Ks = sm + 128 * QST;                  // 128*68
    float* Vs = sm + 128 * (QST + KST);          // 128*72
    float* Ps = sm + 128 * (QST + KST + VST);    // 128*132

    const int tid  = threadIdx.x;
    const int w    = tid >> 5;
    const int lane = tid & 31;
    const int qr   = lane >> 2;      // quad row 0..7
    const int ql   = lane & 3;       // quad lane 0..3
    const int b    = blockIdx.y;
    const int pair = blockIdx.x;

#pragma unroll 1
    for (int half = 0; half < 2; half++) {
        const int qt = half ? (15 - pair) : pair;
        const int q0 = qt * 128;

        // ---- load Q tile (scaled, tf32) ----
        {
            const float* qp = g_q + ((size_t)b * TT + q0) * HH;
#pragma unroll
            for (int t = 0; t < 8; t++) {
                const int idx = tid + t * 256;
                const int r  = idx >> 4;
                const int c4 = (idx & 15) << 2;
                float4 v = *(const float4*)&qp[r * HH + c4];
                uint4 u;
                u.x = f32_to_tf32(v.x * 0.125f); u.y = f32_to_tf32(v.y * 0.125f);
                u.z = f32_to_tf32(v.z * 0.125f); u.w = f32_to_tf32(v.w * 0.125f);
                *(uint4*)&Qs[r * QST + c4] = u;
            }
        }

        float o[8][4];
        float m0 = -1e30f, m1 = -1e30f, l0 = 0.f, l1 = 0.f;
#pragma unroll
        for (int nt = 0; nt < 8; nt++)
#pragma unroll
            for (int r = 0; r < 4; r++) o[nt][r] = 0.f;
        __syncthreads();

#pragma unroll 1
        for (int kt = 0; kt <= qt; kt++) {
            const float* kp = g_k + ((size_t)b * TT + kt * 128) * HH;
            const float* vp = g_v + ((size_t)b * TT + kt * 128) * HH;

            // ---- load K, V tiles (tf32) ----
#pragma unroll
            for (int t = 0; t < 8; t++) {
                const int idx = tid + t * 256;
                const int r  = idx >> 4;
                const int c4 = (idx & 15) << 2;
                float4 kv = *(const float4*)&kp[r * HH + c4];
                uint4 uk;
                uk.x = f32_to_tf32(kv.x); uk.y = f32_to_tf32(kv.y);
                uk.z = f32_to_tf32(kv.z); uk.w = f32_to_tf32(kv.w);
                *(uint4*)&Ks[r * KST + c4] = uk;
                float4 vv = *(const float4*)&vp[r * HH + c4];
                uint4 uv;
                uv.x = f32_to_tf32(vv.x); uv.y = f32_to_tf32(vv.y);
                uv.z = f32_to_tf32(vv.z); uv.w = f32_to_tf32(vv.w);
                *(uint4*)&Vs[r * VST + c4] = uv;
            }
            __syncthreads();

            // ---- S = Q K^T : 16 n-tiles x 8 k-steps ----
            float s[16][4];
#pragma unroll
            for (int nt = 0; nt < 16; nt++)
#pragma unroll
                for (int r = 0; r < 4; r++) s[nt][r] = 0.f;

#pragma unroll
            for (int ks = 0; ks < 8; ks++) {
                const int k0 = ks * 8;
                uint32_t a[4];
                {
                    const int base = (w * 16 + qr) * QST + k0 + ql;
                    a[0] = __float_as_uint(Qs[base]);
                    a[1] = __float_as_uint(Qs[base + 8 * QST]);
                    a[2] = __float_as_uint(Qs[base + 4]);
                    a[3] = __float_as_uint(Qs[base + 8 * QST + 4]);
                }
#pragma unroll
                for (int nt = 0; nt < 16; nt++) {
                    uint32_t bf[2];
                    const int base = (nt * 8 + qr) * KST + k0 + ql;
                    bf[0] = __float_as_uint(Ks[base]);
                    bf[1] = __float_as_uint(Ks[base + 4]);
                    mma_tf32(s[nt], a, bf);
                }
            }

            // ---- causal mask (diagonal tile) ----
            if (kt == qt) {
                const int r0 = w * 16 + qr;
#pragma unroll
                for (int nt = 0; nt < 16; nt++) {
                    const int c = nt * 8 + 2 * ql;
                    if (c     > r0)     s[nt][0] = -1e30f;
                    if (c + 1 > r0)     s[nt][1] = -1e30f;
                    if (c     > r0 + 8) s[nt][2] = -1e30f;
                    if (c + 1 > r0 + 8) s[nt][3] = -1e30f;
                }
            }

            // ---- online softmax on accumulator layout ----
            {
                float mx0 = -1e30f, mx1 = -1e30f;
#pragma unroll
                for (int nt = 0; nt < 16; nt++) {
                    mx0 = fmaxf(mx0, fmaxf(s[nt][0], s[nt][1]));
                    mx1 = fmaxf(mx1, fmaxf(s[nt][2], s[nt][3]));
                }
                mx0 = fmaxf(mx0, __shfl_xor_sync(0xffffffffu, mx0, 1));
                mx0 = fmaxf(mx0, __shfl_xor_sync(0xffffffffu, mx0, 2));
                mx1 = fmaxf(mx1, __shfl_xor_sync(0xffffffffu, mx1, 1));
                mx1 = fmaxf(mx1, __shfl_xor_sync(0xffffffffu, mx1, 2));
                mx0 = fmaxf(mx0, m0);
                mx1 = fmaxf(mx1, m1);

                const float alpha0 = __expf(m0 - mx0);
                const float alpha1 = __expf(m1 - mx1);
                m0 = mx0; m1 = mx1;

                float rs0 = 0.f, rs1 = 0.f;
#pragma unroll
                for (int nt = 0; nt < 16; nt++) {
                    s[nt][0] = __expf(s[nt][0] - mx0);
                    s[nt][1] = __expf(s[nt][1] - mx0);
                    s[nt][2] = __expf(s[nt][2] - mx1);
                    s[nt][3] = __expf(s[nt][3] - mx1);
                    rs0 += s[nt][0] + s[nt][1];
                    rs1 += s[nt][2] + s[nt][3];
                }
                rs0 += __shfl_xor_sync(0xffffffffu, rs0, 1);
                rs0 += __shfl_xor_sync(0xffffffffu, rs0, 2);
                rs1 += __shfl_xor_sync(0xffffffffu, rs1, 1);
                rs1 += __shfl_xor_sync(0xffffffffu, rs1, 2);
                l0 = l0 * alpha0 + rs0;
                l1 = l1 * alpha1 + rs1;

#pragma unroll
                for (int nt = 0; nt < 8; nt++) {
                    o[nt][0] *= alpha0; o[nt][1] *= alpha0;
                    o[nt][2] *= alpha1; o[nt][3] *= alpha1;
                }

                // store P (warp-private rows: no block sync needed)
                const int r0 = w * 16 + qr;
#pragma unroll
                for (int nt = 0; nt < 16; nt++) {
                    float2 t0; t0.x = s[nt][0]; t0.y = s[nt][1];
                    *(float2*)&Ps[r0 * PST + nt * 8 + 2 * ql] = t0;
                    float2 t1; t1.x = s[nt][2]; t1.y = s[nt][3];
                    *(float2*)&Ps[(r0 + 8) * PST + nt * 8 + 2 * ql] = t1;
                }
            }

            // ---- O += P V : 8 n-tiles x 16 k-steps ----
#pragma unroll
            for (int ks = 0; ks < 16; ks++) {
                const int k0 = ks * 8;
                uint32_t a[4];
                {
                    const int base = (w * 16 + qr) * PST + k0 + ql;
                    a[0] = __float_as_uint(Ps[base]);
                    a[1] = __float_as_uint(Ps[base + 8 * PST]);
                    a[2] = __float_as_uint(Ps[base + 4]);
                    a[3] = __float_as_uint(Ps[base + 8 * PST + 4]);
                }
#pragma unroll
                for (int nt = 0; nt < 8; nt++) {
                    uint32_t bf[2];
                    const int base = (k0 + ql) * VST + nt * 8 + qr;
                    bf[0] = __float_as_uint(Vs[base]);
                    bf[1] = __float_as_uint(Vs[base + 4 * VST]);
                    mma_tf32(o[nt], a, bf);
                }
            }
            __syncthreads();
        }

        // ---- epilogue ----
        {
            const float inv0 = 1.f / l0;
            const float inv1 = 1.f / l1;
            const int row = q0 + w * 16 + qr;
#pragma unroll
            for (int nt = 0; nt < 8; nt++) {
                const int c = nt * 8 + 2 * ql;
                float2 t0; t0.x = o[nt][0] * inv0; t0.y = o[nt][1] * inv0;
                *(float2*)&out[((size_t)b * TT + row) * HH + c] = t0;
                float2 t1; t1.x = o[nt][2] * inv1; t1.y = o[nt][3] * inv1;
                *(float2*)&out[((size_t)b * TT + row + 8) * HH + c] = t1;
            }
        }
        __syncthreads();
    }
}

// ===========================================================================
extern "C" void kernel_launch(void* const* d_in, const int* in_sizes, int n_in,
                              void* d_out, int out_size)
{
    (void)in_sizes; (void)n_in; (void)out_size;
    const float* x  = (const float*)d_in[0];
    const float* Wq = (const float*)d_in[1];
    const float* Wk = (const float*)d_in[2];
    const float* Wv = (const float*)d_in[3];
    float* out = (float*)d_out;

    wt_kernel<<<(3 * HH * DD) / 256, 256>>>(Wq, Wk, Wv);

    proj_mma_kernel<<<(BB * TT) / 128, 256>>>(x);

    const int attn_smem = 128 * (QST + KST + VST + PST) * 4;   // 174,080 B
    cudaFuncSetAttribute(attn_kernel,
                         cudaFuncAttributeMaxDynamicSharedMemorySize, attn_smem);
    dim3 g(8, BB);
    attn_kernel<<<g, 256, attn_smem>>>(out);
}